// round 1
// baseline (speedup 1.0000x reference)
#include <cuda_runtime.h>
#include <cstdint>
#include <cstddef>

// Problem constants
#define H_    4
#define DM_   512
#define DK_   128
#define B_    1024
#define LQ_   32
#define LK_   64

// ---------------- scratch (device globals; no allocation allowed) ----------
__device__ float g_wqeff[H_ * DM_];                       //  8 KB
__device__ float g_wkeff[H_ * DM_];                       //  8 KB
__device__ float g_attn[(size_t)H_ * B_ * LQ_ * LK_];     //  33 MB
__device__ float g_vp[(size_t)B_ * LK_ * DM_];            // 134 MB
__device__ float g_oattn[(size_t)B_ * LQ_ * DM_];         //  67 MB
__device__ float g_fcout[(size_t)B_ * LQ_ * DM_];         //  67 MB
__device__ int   g_maskmode;                              // 0=bool8 1=int32 2=float32

// ---------------- mask dtype detection -------------------------------------
// Safe: reads only 4096 bytes (allocation is >= 2 MB for any dtype).
// float32 0/1 data contains bytes 0x80/0x3F; bool has nonzero bytes at i%4!=0;
// int32 0/1 has nonzero only at i%4==0.
__global__ void detect_mask_kernel(const unsigned char* __restrict__ m) {
    __shared__ int f0, f1;
    if (threadIdx.x == 0) { f0 = 0; f1 = 0; }
    __syncthreads();
    int lf = 0, lb = 0;
    for (int i = threadIdx.x; i < 4096; i += blockDim.x) {
        unsigned char c = m[i];
        if (c == 0x3Fu || c == 0x80u) lf = 1;
        if (c != 0u && (i & 3) != 0) lb = 1;
    }
    if (lf) atomicOr(&f0, 1);
    if (lb) atomicOr(&f1, 1);
    __syncthreads();
    if (threadIdx.x == 0) g_maskmode = f0 ? 2 : (f1 ? 0 : 1);
}

__device__ __forceinline__ bool load_mask(const void* m, int mode, size_t idx) {
    if (mode == 2) return ((const float*)m)[idx] != 0.0f;
    if (mode == 1) return ((const int*)m)[idx] != 0;
    return ((const unsigned char*)m)[idx] != 0u;
}

// ---------------- effective map weights ------------------------------------
// wq_eff[h][dm] = sum_d wm_q[d] * Wq[(h*128+d)*512 + dm]   (same for k side)
__global__ void weff_kernel(const float* __restrict__ Wq,
                            const float* __restrict__ Wk,
                            const float* __restrict__ Wmap) {
    int t = blockIdx.x * blockDim.x + threadIdx.x;
    if (t >= 2 * H_ * DM_) return;
    int isK = t >= H_ * DM_;
    int r = isK ? (t - H_ * DM_) : t;
    int h = r / DM_, dm = r % DM_;
    const float* W  = isK ? Wk : Wq;
    const float* wm = Wmap + (isK ? DK_ : 0);
    float s = 0.f;
    #pragma unroll 8
    for (int d = 0; d < DK_; d++)
        s += wm[d] * W[(size_t)(h * DK_ + d) * DM_ + dm];
    if (isK) g_wkeff[r] = s; else g_wqeff[r] = s;
}

// ---------------- fused scores + softmax + attn write ----------------------
// one block per batch b; computes sq (32 rows x 4 heads) and sk (64 rows x 4
// heads) reading q/k rows exactly once, then warp-per-(h,q) softmax over 64 k.
__global__ __launch_bounds__(256) void attn_kernel(
    const float* __restrict__ qin, const float* __restrict__ kin,
    const void* __restrict__ mask, float* __restrict__ attn_out, int write_out)
{
    __shared__ float wS[2 * H_ * DM_];  // wq_eff then wk_eff, 16 KB
    __shared__ float sqS[H_ * LQ_];
    __shared__ float skS[H_ * LK_];
    const int b = blockIdx.x;
    const int tid = threadIdx.x, warp = tid >> 5, lane = tid & 31;

    for (int i = tid; i < H_ * DM_; i += 256) {
        wS[i]            = g_wqeff[i];
        wS[H_ * DM_ + i] = g_wkeff[i];
    }
    __syncthreads();

    // 96 row-dots per block (32 q rows + 64 k rows), 4 heads each
    for (int j = warp; j < LQ_ + LK_; j += 8) {
        const float* vec;
        const float* wf;
        if (j < LQ_) { vec = qin + ((size_t)b * LQ_ + j) * DM_;        wf = wS; }
        else         { vec = kin + ((size_t)b * LK_ + (j - LQ_)) * DM_; wf = wS + H_ * DM_; }
        float s0 = 0.f, s1 = 0.f, s2 = 0.f, s3 = 0.f;
        for (int idx = lane; idx < DM_; idx += 32) {
            float x = vec[idx];
            s0 += x * wf[idx];
            s1 += x * wf[DM_ + idx];
            s2 += x * wf[2 * DM_ + idx];
            s3 += x * wf[3 * DM_ + idx];
        }
        #pragma unroll
        for (int o = 16; o; o >>= 1) {
            s0 += __shfl_xor_sync(0xffffffffu, s0, o);
            s1 += __shfl_xor_sync(0xffffffffu, s1, o);
            s2 += __shfl_xor_sync(0xffffffffu, s2, o);
            s3 += __shfl_xor_sync(0xffffffffu, s3, o);
        }
        if (lane == 0) {
            if (j < LQ_) {
                sqS[0 * LQ_ + j] = s0; sqS[1 * LQ_ + j] = s1;
                sqS[2 * LQ_ + j] = s2; sqS[3 * LQ_ + j] = s3;
            } else {
                int kk = j - LQ_;
                skS[0 * LK_ + kk] = s0; skS[1 * LK_ + kk] = s1;
                skS[2 * LK_ + kk] = s2; skS[3 * LK_ + kk] = s3;
            }
        }
    }
    __syncthreads();

    const int mm = g_maskmode;
    for (int r = warp; r < H_ * LQ_; r += 8) {
        const int h = r >> 5, qq = r & 31;
        const float sq = sqS[r];
        const size_t mbase = ((size_t)b * LQ_ + qq) * LK_;
        bool m0 = load_mask(mask, mm, mbase + lane);
        bool m1 = load_mask(mask, mm, mbase + lane + 32);
        float v0 = m0 ? -1e10f : sq + skS[h * LK_ + lane];
        float v1 = m1 ? -1e10f : sq + skS[h * LK_ + lane + 32];
        float mx = fmaxf(v0, v1);
        #pragma unroll
        for (int o = 16; o; o >>= 1) mx = fmaxf(mx, __shfl_xor_sync(0xffffffffu, mx, o));
        float p0 = expf(v0 - mx), p1 = expf(v1 - mx);
        float sm = p0 + p1;
        #pragma unroll
        for (int o = 16; o; o >>= 1) sm += __shfl_xor_sync(0xffffffffu, sm, o);
        float inv = 1.0f / sm;
        p0 *= inv; p1 *= inv;
        const size_t ob = (((size_t)h * B_ + b) * LQ_ + qq) * LK_;
        g_attn[ob + lane]      = p0;
        g_attn[ob + lane + 32] = p1;
        if (write_out) {
            attn_out[ob + lane]      = p0;
            attn_out[ob + lane + 32] = p1;
        }
    }
}

// ---------------- fp32 SGEMM:  C[M,N] = A[M,K] * W[N,K]^T ------------------
#define BM 128
#define BN 128
#define BKK 16
__global__ __launch_bounds__(256) void sgemm_nt(
    const float* __restrict__ A, const float* __restrict__ W,
    float* __restrict__ C, int M, int N, int K)
{
    __shared__ float As[BKK][BM + 4];
    __shared__ float Ws[BKK][BN + 4];
    const int tid = threadIdx.x;
    const int bm = blockIdx.y * BM;
    const int bn = blockIdx.x * BN;
    const int tx = tid & 15;        // n dir
    const int ty = tid >> 4;        // m dir
    const int lRow = tid >> 2;      // 0..63
    const int lCol = (tid & 3) << 2;

    float acc[8][8];
    #pragma unroll
    for (int i = 0; i < 8; i++)
        #pragma unroll
        for (int j = 0; j < 8; j++) acc[i][j] = 0.f;

    for (int k0 = 0; k0 < K; k0 += BKK) {
        #pragma unroll
        for (int rr = 0; rr < 2; rr++) {
            const float4 a = *reinterpret_cast<const float4*>(
                &A[(size_t)(bm + lRow + rr * 64) * K + k0 + lCol]);
            As[lCol + 0][lRow + rr * 64] = a.x;
            As[lCol + 1][lRow + rr * 64] = a.y;
            As[lCol + 2][lRow + rr * 64] = a.z;
            As[lCol + 3][lRow + rr * 64] = a.w;
            const float4 w = *reinterpret_cast<const float4*>(
                &W[(size_t)(bn + lRow + rr * 64) * K + k0 + lCol]);
            Ws[lCol + 0][lRow + rr * 64] = w.x;
            Ws[lCol + 1][lRow + rr * 64] = w.y;
            Ws[lCol + 2][lRow + rr * 64] = w.z;
            Ws[lCol + 3][lRow + rr * 64] = w.w;
        }
        __syncthreads();
        #pragma unroll
        for (int kk = 0; kk < BKK; kk++) {
            float a[8], bb[8];
            #pragma unroll
            for (int i = 0; i < 8; i++) a[i] = As[kk][ty * 8 + i];
            #pragma unroll
            for (int j = 0; j < 8; j++) bb[j] = Ws[kk][tx * 8 + j];
            #pragma unroll
            for (int i = 0; i < 8; i++)
                #pragma unroll
                for (int j = 0; j < 8; j++) acc[i][j] += a[i] * bb[j];
        }
        __syncthreads();
    }
    #pragma unroll
    for (int i = 0; i < 8; i++) {
        #pragma unroll
        for (int j = 0; j < 8; j += 4) {
            float4 v;
            v.x = acc[i][j]; v.y = acc[i][j + 1]; v.z = acc[i][j + 2]; v.w = acc[i][j + 3];
            *reinterpret_cast<float4*>(
                &C[(size_t)(bm + ty * 8 + i) * N + bn + tx * 8 + j]) = v;
        }
    }
}

// ---------------- attn @ vp  -> g_oattn -------------------------------------
// out[b,q,h*128+d] = sum_k attn[h,b,q,k] * vp[(b*64+k)*512 + h*128+d]
__global__ __launch_bounds__(256) void av_kernel() {
    const int b = blockIdx.x;
    __shared__ float aS[H_ * LQ_ * LK_];  // 32 KB
    for (int i = threadIdx.x; i < H_ * LQ_ * LK_; i += 256) {
        int h = i >> 11;           // 2048 = 32*64 per head
        int rem = i & 2047;
        aS[i] = g_attn[(((size_t)h * B_ + b) * LQ_) * LK_ + rem];
    }
    __syncthreads();
    #pragma unroll
    for (int c0 = 0; c0 < 2; c0++) {
        const int col = threadIdx.x + c0 * 256;
        const int h = col >> 7;
        float acc[LQ_];
        #pragma unroll
        for (int q = 0; q < LQ_; q++) acc[q] = 0.f;
        const float* vpb = g_vp + (size_t)b * LK_ * DM_ + col;
        const float* aH = aS + h * LQ_ * LK_;
        for (int kk = 0; kk < LK_; kk++) {
            float vv = vpb[(size_t)kk * DM_];
            #pragma unroll
            for (int q = 0; q < LQ_; q++) acc[q] += aH[q * LK_ + kk] * vv;
        }
        #pragma unroll
        for (int q = 0; q < LQ_; q++)
            g_oattn[((size_t)b * LQ_ + q) * DM_ + col] = acc[q];
    }
}

// ---------------- bias + leakyReLU + residual + LayerNorm ------------------
__global__ __launch_bounds__(128) void epilogue_kernel(
    const float* __restrict__ qin, const float* __restrict__ fcb,
    const float* __restrict__ gamma, const float* __restrict__ beta,
    float* __restrict__ out)
{
    const int row = blockIdx.x;            // b*32 + q
    const int tid = threadIdx.x;
    __shared__ float rs[8];
    float y[4];
    float s = 0.f, s2 = 0.f;
    #pragma unroll
    for (int i = 0; i < 4; i++) {
        int j = tid + i * 128;
        float x = g_fcout[(size_t)row * DM_ + j] + fcb[j];
        x = (x >= 0.f) ? x : 0.2f * x;
        x += qin[(size_t)row * DM_ + j];
        y[i] = x; s += x; s2 += x * x;
    }
    #pragma unroll
    for (int o = 16; o; o >>= 1) {
        s  += __shfl_xor_sync(0xffffffffu, s, o);
        s2 += __shfl_xor_sync(0xffffffffu, s2, o);
    }
    const int warp = tid >> 5, lane = tid & 31;
    if (lane == 0) { rs[warp] = s; rs[4 + warp] = s2; }
    __syncthreads();
    s  = rs[0] + rs[1] + rs[2] + rs[3];
    s2 = rs[4] + rs[5] + rs[6] + rs[7];
    const float mu  = s * (1.0f / DM_);
    const float var = s2 * (1.0f / DM_) - mu * mu;
    const float inv = rsqrtf(var + 1e-5f);
    #pragma unroll
    for (int i = 0; i < 4; i++) {
        int j = tid + i * 128;
        out[(size_t)row * DM_ + j] = gamma[j] * (y[i] - mu) * inv + beta[j];
    }
}

// ---------------- launch ----------------------------------------------------
extern "C" void kernel_launch(void* const* d_in, const int* in_sizes, int n_in,
                              void* d_out, int out_size)
{
    const float* q    = (const float*)d_in[0];
    const float* k    = (const float*)d_in[1];
    const float* v    = (const float*)d_in[2];
    const void*  mask =               d_in[3];
    const float* Wq   = (const float*)d_in[4];
    const float* Wk   = (const float*)d_in[5];
    const float* Wv   = (const float*)d_in[6];
    const float* Wmap = (const float*)d_in[7];
    const float* fcW  = (const float*)d_in[8];
    const float* fcb  = (const float*)d_in[9];
    const float* gma  = (const float*)d_in[10];
    const float* bta  = (const float*)d_in[11];
    float* out = (float*)d_out;

    const size_t out_elems  = (size_t)B_ * LQ_ * DM_;           // 16,777,216
    const size_t attn_elems = (size_t)H_ * B_ * LQ_ * LK_;      //  8,388,608
    int write_attn = ((size_t)out_size >= out_elems + attn_elems) ? 1 : 0;
    float* attn_out = out + out_elems;

    void *p_vp = nullptr, *p_oattn = nullptr, *p_fcout = nullptr;
    cudaGetSymbolAddress(&p_vp, g_vp);
    cudaGetSymbolAddress(&p_oattn, g_oattn);
    cudaGetSymbolAddress(&p_fcout, g_fcout);

    detect_mask_kernel<<<1, 256>>>((const unsigned char*)mask);
    weff_kernel<<<(2 * H_ * DM_ + 255) / 256, 256>>>(Wq, Wk, Wmap);
    attn_kernel<<<B_, 256>>>(q, k, mask, attn_out, write_attn);

    // vp = v @ Wv^T : M = B*LK = 65536, N = 512, K = 512
    {
        dim3 grid(DM_ / BN, (B_ * LK_) / BM);
        sgemm_nt<<<grid, 256>>>(v, Wv, (float*)p_vp, B_ * LK_, DM_, DM_);
    }

    av_kernel<<<B_, 256>>>();

    // fc = oattn @ fcW^T : M = B*LQ = 32768, N = 512, K = 512
    {
        dim3 grid(DM_ / BN, (B_ * LQ_) / BM);
        sgemm_nt<<<grid, 256>>>((const float*)p_oattn, fcW, (float*)p_fcout,
                                B_ * LQ_, DM_, DM_);
    }

    epilogue_kernel<<<B_ * LQ_, 128>>>(q, fcb, gma, bta, out);
}

// round 3
// speedup vs baseline: 1.2955x; 1.2955x over previous
#include <cuda_runtime.h>
#include <cstdint>
#include <cstddef>

// Problem constants
#define H_    4
#define DM_   512
#define DK_   128
#define B_    1024
#define LQ_   32
#define LK_   64

// ---------------- scratch (device globals; no allocation allowed) ----------
__device__ float g_wqeff[H_ * DM_];
__device__ float g_wkeff[H_ * DM_];
__device__ float g_attn[(size_t)H_ * B_ * LQ_ * LK_];     //  33 MB
__device__ float g_vp[(size_t)B_ * LK_ * DM_];            // 134 MB
__device__ float g_oattn[(size_t)B_ * LQ_ * DM_];         //  67 MB
__device__ float g_fcout[(size_t)B_ * LQ_ * DM_];         //  67 MB
__device__ int   g_maskmode;

__device__ __forceinline__ float to_tf32(float x) {
    float y; asm("cvt.rna.tf32.f32 %0, %1;" : "=f"(y) : "f"(x)); return y;
}

__device__ __forceinline__ void mma_tf32(float* c,
                                         uint32_t a0, uint32_t a1, uint32_t a2, uint32_t a3,
                                         uint32_t b0, uint32_t b1) {
    asm volatile("mma.sync.aligned.m16n8k8.row.col.f32.tf32.tf32.f32 "
                 "{%0,%1,%2,%3}, {%4,%5,%6,%7}, {%8,%9}, {%0,%1,%2,%3};"
                 : "+f"(c[0]), "+f"(c[1]), "+f"(c[2]), "+f"(c[3])
                 : "r"(a0), "r"(a1), "r"(a2), "r"(a3), "r"(b0), "r"(b1));
}

// ====================== tf32 mma.sync GEMM:  C = A * W^T ====================
// A[M,512] row-major, W[512,512] row-major ([N,K] row-major == col-layout B).
// CTA tile 128x128, K-tile 32, 8 warps (2 m x 4 n), warp tile 64x32.
#define BM 128
#define BN 128
#define BK 32
#define NKT (DM_ / BK)       // 16
#define SA  132              // smem row stride (floats), conflict-free
#define TILE_F (BK * SA)     // floats per buffer

__global__ void __launch_bounds__(256, 2) tmma_tf32(
    const float* __restrict__ A, const float* __restrict__ W,
    float* __restrict__ C)
{
    extern __shared__ float sm[];
    float* Asb[2] = { sm,              sm + TILE_F };
    float* Wsb[2] = { sm + 2 * TILE_F, sm + 3 * TILE_F };

    const int tid  = threadIdx.x;
    const int wid  = tid >> 5, lane = tid & 31;
    const int gid  = lane >> 2;       // 0..7
    const int tg   = lane & 3;        // 0..3
    const int wm   = wid >> 2;        // 0..1  -> m offset wm*64
    const int wn   = wid & 3;         // 0..3  -> n offset wn*32
    const int bm   = blockIdx.y * BM;
    const int bn   = blockIdx.x * BN;

    const int lrow = tid & 127;       // row handled by this thread in ld
    const int lk0  = (tid >> 7) * 16; // k half: 0 or 16

    const float* Ag = A + (size_t)(bm + lrow) * DM_ + lk0;
    const float* Wg = W + (size_t)(bn + lrow) * DM_ + lk0;

    float acc[4][4][4];
    #pragma unroll
    for (int i = 0; i < 4; i++)
        #pragma unroll
        for (int j = 0; j < 4; j++)
            #pragma unroll
            for (int r = 0; r < 4; r++) acc[i][j][r] = 0.f;

    auto load_tile = [&](int kt, int buf) {
        const float* ap = Ag + kt * BK;
        const float* wp = Wg + kt * BK;
        float* as = Asb[buf];
        float* ws = Wsb[buf];
        #pragma unroll
        for (int j4 = 0; j4 < 4; j4++) {
            float4 v = *(const float4*)(ap + j4 * 4);
            int kk = lk0 + j4 * 4;
            as[(kk + 0) * SA + lrow] = to_tf32(v.x);
            as[(kk + 1) * SA + lrow] = to_tf32(v.y);
            as[(kk + 2) * SA + lrow] = to_tf32(v.z);
            as[(kk + 3) * SA + lrow] = to_tf32(v.w);
            float4 u = *(const float4*)(wp + j4 * 4);
            ws[(kk + 0) * SA + lrow] = to_tf32(u.x);
            ws[(kk + 1) * SA + lrow] = to_tf32(u.y);
            ws[(kk + 2) * SA + lrow] = to_tf32(u.z);
            ws[(kk + 3) * SA + lrow] = to_tf32(u.w);
        }
    };

    load_tile(0, 0);
    __syncthreads();

    for (int kt = 0; kt < NKT; kt++) {
        const int buf = kt & 1;
        if (kt + 1 < NKT) load_tile(kt + 1, buf ^ 1);

        const float* as = Asb[buf];
        const float* ws = Wsb[buf];
        #pragma unroll
        for (int ks = 0; ks < BK; ks += 8) {
            uint32_t af[4][4];
            #pragma unroll
            for (int mt = 0; mt < 4; mt++) {
                const int rb = wm * 64 + mt * 16 + gid;
                af[mt][0] = __float_as_uint(as[(ks + tg)     * SA + rb]);
                af[mt][1] = __float_as_uint(as[(ks + tg)     * SA + rb + 8]);
                af[mt][2] = __float_as_uint(as[(ks + 4 + tg) * SA + rb]);
                af[mt][3] = __float_as_uint(as[(ks + 4 + tg) * SA + rb + 8]);
            }
            uint32_t bf[4][2];
            #pragma unroll
            for (int nt = 0; nt < 4; nt++) {
                const int cb = wn * 32 + nt * 8 + gid;
                bf[nt][0] = __float_as_uint(ws[(ks + tg)     * SA + cb]);
                bf[nt][1] = __float_as_uint(ws[(ks + 4 + tg) * SA + cb]);
            }
            #pragma unroll
            for (int mt = 0; mt < 4; mt++)
                #pragma unroll
                for (int nt = 0; nt < 4; nt++)
                    mma_tf32(acc[mt][nt],
                             af[mt][0], af[mt][1], af[mt][2], af[mt][3],
                             bf[nt][0], bf[nt][1]);
        }
        __syncthreads();
    }

    // ---- store C ----
    #pragma unroll
    for (int mt = 0; mt < 4; mt++) {
        const int row0 = bm + wm * 64 + mt * 16 + gid;
        #pragma unroll
        for (int nt = 0; nt < 4; nt++) {
            const int col0 = bn + wn * 32 + nt * 8 + tg * 2;
            float2 v0 = make_float2(acc[mt][nt][0], acc[mt][nt][1]);
            float2 v1 = make_float2(acc[mt][nt][2], acc[mt][nt][3]);
            *(float2*)(C + (size_t)row0 * DM_ + col0)       = v0;
            *(float2*)(C + (size_t)(row0 + 8) * DM_ + col0) = v1;
        }
    }
}

// ---------------- mask dtype detection -------------------------------------
__global__ void detect_mask_kernel(const unsigned char* __restrict__ m) {
    __shared__ int f0, f1;
    if (threadIdx.x == 0) { f0 = 0; f1 = 0; }
    __syncthreads();
    int lf = 0, lb = 0;
    for (int i = threadIdx.x; i < 4096; i += blockDim.x) {
        unsigned char c = m[i];
        if (c == 0x3Fu || c == 0x80u) lf = 1;
        if (c != 0u && (i & 3) != 0) lb = 1;
    }
    if (lf) atomicOr(&f0, 1);
    if (lb) atomicOr(&f1, 1);
    __syncthreads();
    if (threadIdx.x == 0) g_maskmode = f0 ? 2 : (f1 ? 0 : 1);
}

__device__ __forceinline__ bool load_mask(const void* m, int mode, size_t idx) {
    if (mode == 2) return ((const float*)m)[idx] != 0.0f;
    if (mode == 1) return ((const int*)m)[idx] != 0;
    return ((const unsigned char*)m)[idx] != 0u;
}

// ---------------- effective map weights ------------------------------------
__global__ void weff_kernel(const float* __restrict__ Wq,
                            const float* __restrict__ Wk,
                            const float* __restrict__ Wmap) {
    int t = blockIdx.x * blockDim.x + threadIdx.x;
    if (t >= 2 * H_ * DM_) return;
    int isK = t >= H_ * DM_;
    int r = isK ? (t - H_ * DM_) : t;
    int h = r / DM_, dm = r % DM_;
    const float* W  = isK ? Wk : Wq;
    const float* wm = Wmap + (isK ? DK_ : 0);
    float s = 0.f;
    #pragma unroll 8
    for (int d = 0; d < DK_; d++)
        s += wm[d] * W[(size_t)(h * DK_ + d) * DM_ + dm];
    if (isK) g_wkeff[r] = s; else g_wqeff[r] = s;
}

// ---------------- fused scores + softmax + attn write ----------------------
__global__ __launch_bounds__(256) void attn_kernel(
    const float* __restrict__ qin, const float* __restrict__ kin,
    const void* __restrict__ mask, float* __restrict__ attn_out, int write_out)
{
    __shared__ float wS[2 * H_ * DM_];
    __shared__ float sqS[H_ * LQ_];
    __shared__ float skS[H_ * LK_];
    const int b = blockIdx.x;
    const int tid = threadIdx.x, warp = tid >> 5, lane = tid & 31;

    for (int i = tid; i < H_ * DM_; i += 256) {
        wS[i]            = g_wqeff[i];
        wS[H_ * DM_ + i] = g_wkeff[i];
    }
    __syncthreads();

    for (int j = warp; j < LQ_ + LK_; j += 8) {
        const float* vec;
        const float* wf;
        if (j < LQ_) { vec = qin + ((size_t)b * LQ_ + j) * DM_;         wf = wS; }
        else         { vec = kin + ((size_t)b * LK_ + (j - LQ_)) * DM_; wf = wS + H_ * DM_; }
        float s0 = 0.f, s1 = 0.f, s2 = 0.f, s3 = 0.f;
        for (int idx = lane; idx < DM_; idx += 32) {
            float x = vec[idx];
            s0 += x * wf[idx];
            s1 += x * wf[DM_ + idx];
            s2 += x * wf[2 * DM_ + idx];
            s3 += x * wf[3 * DM_ + idx];
        }
        #pragma unroll
        for (int o = 16; o; o >>= 1) {
            s0 += __shfl_xor_sync(0xffffffffu, s0, o);
            s1 += __shfl_xor_sync(0xffffffffu, s1, o);
            s2 += __shfl_xor_sync(0xffffffffu, s2, o);
            s3 += __shfl_xor_sync(0xffffffffu, s3, o);
        }
        if (lane == 0) {
            if (j < LQ_) {
                sqS[0 * LQ_ + j] = s0; sqS[1 * LQ_ + j] = s1;
                sqS[2 * LQ_ + j] = s2; sqS[3 * LQ_ + j] = s3;
            } else {
                int kk = j - LQ_;
                skS[0 * LK_ + kk] = s0; skS[1 * LK_ + kk] = s1;
                skS[2 * LK_ + kk] = s2; skS[3 * LK_ + kk] = s3;
            }
        }
    }
    __syncthreads();

    const int mm = g_maskmode;
    for (int r = warp; r < H_ * LQ_; r += 8) {
        const int h = r >> 5, qq = r & 31;
        const float sq = sqS[r];
        const size_t mbase = ((size_t)b * LQ_ + qq) * LK_;
        bool m0 = load_mask(mask, mm, mbase + lane);
        bool m1 = load_mask(mask, mm, mbase + lane + 32);
        float v0 = m0 ? -1e10f : sq + skS[h * LK_ + lane];
        float v1 = m1 ? -1e10f : sq + skS[h * LK_ + lane + 32];
        float mx = fmaxf(v0, v1);
        #pragma unroll
        for (int o = 16; o; o >>= 1) mx = fmaxf(mx, __shfl_xor_sync(0xffffffffu, mx, o));
        float p0 = expf(v0 - mx), p1 = expf(v1 - mx);
        float sm = p0 + p1;
        #pragma unroll
        for (int o = 16; o; o >>= 1) sm += __shfl_xor_sync(0xffffffffu, sm, o);
        float inv = 1.0f / sm;
        p0 *= inv; p1 *= inv;
        const size_t ob = (((size_t)h * B_ + b) * LQ_ + qq) * LK_;
        g_attn[ob + lane]      = p0;
        g_attn[ob + lane + 32] = p1;
        if (write_out) {
            attn_out[ob + lane]      = p0;
            attn_out[ob + lane + 32] = p1;
        }
    }
}

// ---------------- attn @ vp  -> g_oattn -------------------------------------
__global__ __launch_bounds__(256) void av_kernel() {
    const int b = blockIdx.x;
    __shared__ float aS[H_ * LQ_ * LK_];
    for (int i = threadIdx.x; i < H_ * LQ_ * LK_; i += 256) {
        int h = i >> 11;
        int rem = i & 2047;
        aS[i] = g_attn[(((size_t)h * B_ + b) * LQ_) * LK_ + rem];
    }
    __syncthreads();
    #pragma unroll
    for (int c0 = 0; c0 < 2; c0++) {
        const int col = threadIdx.x + c0 * 256;
        const int h = col >> 7;
        float acc[LQ_];
        #pragma unroll
        for (int q = 0; q < LQ_; q++) acc[q] = 0.f;
        const float* vpb = g_vp + (size_t)b * LK_ * DM_ + col;
        const float* aH = aS + h * LQ_ * LK_;
        for (int kk = 0; kk < LK_; kk++) {
            float vv = vpb[(size_t)kk * DM_];
            #pragma unroll
            for (int q = 0; q < LQ_; q++) acc[q] += aH[q * LK_ + kk] * vv;
        }
        #pragma unroll
        for (int q = 0; q < LQ_; q++)
            g_oattn[((size_t)b * LQ_ + q) * DM_ + col] = acc[q];
    }
}

// ---------------- bias + leakyReLU + residual + LayerNorm ------------------
__global__ __launch_bounds__(128) void epilogue_kernel(
    const float* __restrict__ qin, const float* __restrict__ fcb,
    const float* __restrict__ gamma, const float* __restrict__ beta,
    float* __restrict__ out)
{
    const int row = blockIdx.x;
    const int tid = threadIdx.x;
    __shared__ float rs[8];
    float y[4];
    float s = 0.f, s2 = 0.f;
    #pragma unroll
    for (int i = 0; i < 4; i++) {
        int j = tid + i * 128;
        float x = g_fcout[(size_t)row * DM_ + j] + fcb[j];
        x = (x >= 0.f) ? x : 0.2f * x;
        x += qin[(size_t)row * DM_ + j];
        y[i] = x; s += x; s2 += x * x;
    }
    #pragma unroll
    for (int o = 16; o; o >>= 1) {
        s  += __shfl_xor_sync(0xffffffffu, s, o);
        s2 += __shfl_xor_sync(0xffffffffu, s2, o);
    }
    const int warp = tid >> 5, lane = tid & 31;
    if (lane == 0) { rs[warp] = s; rs[4 + warp] = s2; }
    __syncthreads();
    s  = rs[0] + rs[1] + rs[2] + rs[3];
    s2 = rs[4] + rs[5] + rs[6] + rs[7];
    const float mu  = s * (1.0f / DM_);
    const float var = s2 * (1.0f / DM_) - mu * mu;
    const float inv = rsqrtf(var + 1e-5f);
    #pragma unroll
    for (int i = 0; i < 4; i++) {
        int j = tid + i * 128;
        out[(size_t)row * DM_ + j] = gamma[j] * (y[i] - mu) * inv + beta[j];
    }
}

// ---------------- launch ----------------------------------------------------
extern "C" void kernel_launch(void* const* d_in, const int* in_sizes, int n_in,
                              void* d_out, int out_size)
{
    const float* q    = (const float*)d_in[0];
    const float* k    = (const float*)d_in[1];
    const float* v    = (const float*)d_in[2];
    const void*  mask =               d_in[3];
    const float* Wq   = (const float*)d_in[4];
    const float* Wk   = (const float*)d_in[5];
    const float* Wv   = (const float*)d_in[6];
    const float* Wmap = (const float*)d_in[7];
    const float* fcW  = (const float*)d_in[8];
    const float* fcb  = (const float*)d_in[9];
    const float* gma  = (const float*)d_in[10];
    const float* bta  = (const float*)d_in[11];
    float* out = (float*)d_out;

    const size_t out_elems  = (size_t)B_ * LQ_ * DM_;
    const size_t attn_elems = (size_t)H_ * B_ * LQ_ * LK_;
    int write_attn = ((size_t)out_size >= out_elems + attn_elems) ? 1 : 0;
    float* attn_out = out + out_elems;

    void *p_vp = nullptr, *p_oattn = nullptr, *p_fcout = nullptr;
    cudaGetSymbolAddress(&p_vp, g_vp);
    cudaGetSymbolAddress(&p_oattn, g_oattn);
    cudaGetSymbolAddress(&p_fcout, g_fcout);

    const int smem_bytes = 4 * TILE_F * sizeof(float);   // 67584
    cudaFuncSetAttribute(tmma_tf32, cudaFuncAttributeMaxDynamicSharedMemorySize, smem_bytes);

    detect_mask_kernel<<<1, 256>>>((const unsigned char*)mask);
    weff_kernel<<<(2 * H_ * DM_ + 255) / 256, 256>>>(Wq, Wk, Wmap);
    attn_kernel<<<B_, 256>>>(q, k, mask, attn_out, write_attn);

    // vp = v @ Wv^T : M = 65536, N = 512, K = 512
    {
        dim3 grid(DM_ / BN, (B_ * LK_) / BM);
        tmma_tf32<<<grid, 256, smem_bytes>>>(v, Wv, (float*)p_vp);
    }

    av_kernel<<<B_, 256>>>();

    // fc = oattn @ fcW^T : M = 32768, N = 512, K = 512
    {
        dim3 grid(DM_ / BN, (B_ * LQ_) / BM);
        tmma_tf32<<<grid, 256, smem_bytes>>>((const float*)p_oattn, fcW, (float*)p_fcout);
    }

    epilogue_kernel<<<B_ * LQ_, 128>>>(q, fcb, gma, bta, out);
}

// round 4
// speedup vs baseline: 2.3053x; 1.7795x over previous
#include <cuda_runtime.h>
#include <cstdint>
#include <cstddef>

// Problem constants
#define H_    4
#define DM_   512
#define DK_   128
#define B_    1024
#define LQ_   32
#define LK_   64

// ---------------- scratch (device globals; no allocation allowed) ----------
__device__ float g_wqeff[H_ * DM_];
__device__ float g_wkeff[H_ * DM_];
__device__ float g_attn[(size_t)H_ * B_ * LQ_ * LK_];     //  33 MB
__device__ float g_vp[(size_t)B_ * LK_ * DM_];            // 134 MB
__device__ float g_oattn[(size_t)B_ * LQ_ * DM_];         //  67 MB
__device__ float g_fcout[(size_t)B_ * LQ_ * DM_];         //  67 MB
__device__ int   g_maskmode;

__device__ __forceinline__ uint32_t smem_u32(const void* p) {
    uint32_t a;
    asm("{ .reg .u64 t; cvta.to.shared.u64 t, %1; cvt.u32.u64 %0, t; }"
        : "=r"(a) : "l"(p));
    return a;
}
__device__ __forceinline__ void cp_async16(uint32_t dst, const void* src) {
    asm volatile("cp.async.cg.shared.global [%0], [%1], 16;" :: "r"(dst), "l"(src));
}
#define CP_COMMIT() asm volatile("cp.async.commit_group;" ::: "memory")
#define CP_WAIT1()  asm volatile("cp.async.wait_group 1;" ::: "memory")

__device__ __forceinline__ void mma_tf32(float* c,
                                         uint32_t a0, uint32_t a1, uint32_t a2, uint32_t a3,
                                         uint32_t b0, uint32_t b1) {
    asm volatile("mma.sync.aligned.m16n8k8.row.col.f32.tf32.tf32.f32 "
                 "{%0,%1,%2,%3}, {%4,%5,%6,%7}, {%8,%9}, {%0,%1,%2,%3};"
                 : "+f"(c[0]), "+f"(c[1]), "+f"(c[2]), "+f"(c[3])
                 : "r"(a0), "r"(a1), "r"(a2), "r"(a3), "r"(b0), "r"(b1));
}

// ====================== tf32 mma.sync GEMM:  C = A * W^T ====================
// A[M,512] row-major, W[512,512] row-major ([N,K] row-major == col-layout B).
// CTA tile 128x128, K-tile 32, 4 warps (2m x 2n), warp tile 64x64.
// cp.async 3-stage pipeline; smem row-major stride 36 (conflict-free frags).
#define BM 128
#define BN 128
#define BK 32
#define NKT (DM_ / BK)       // 16
#define STG 3
#define SROW 36
#define ATILE_F (BM * SROW)          // 4608 floats
#define STILE_F (2 * ATILE_F)        // A + B per stage
#define GEMM_SMEM_BYTES (STG * STILE_F * 4)   // 110592

__global__ void __launch_bounds__(128, 2) tmma_tf32(
    const float* __restrict__ A, const float* __restrict__ W,
    float* __restrict__ C)
{
    extern __shared__ float sm[];
    const int tid  = threadIdx.x;
    const int wid  = tid >> 5, lane = tid & 31;
    const int gid  = lane >> 2;       // 0..7
    const int tg   = lane & 3;        // 0..3
    const int wm   = wid >> 1;        // 0..1 -> m offset wm*64
    const int wn   = wid & 1;         // 0..1 -> n offset wn*64
    const int bm   = blockIdx.y * BM;
    const int bn   = blockIdx.x * BN;
    const uint32_t sbase = smem_u32(sm);

    float acc[4][8][4];
    #pragma unroll
    for (int i = 0; i < 4; i++)
        #pragma unroll
        for (int j = 0; j < 8; j++)
            #pragma unroll
            for (int r = 0; r < 4; r++) acc[i][j][r] = 0.f;

    // loader: thread covers rows (tid>>3)+16i, 16B chunk (tid&7)*4 within k-tile
    const int r0 = tid >> 3;
    const int kc = (tid & 7) * 4;
    const float* ga0 = A + (size_t)(bm + r0) * DM_ + kc;
    const float* gb0 = W + (size_t)(bn + r0) * DM_ + kc;

    auto load_tile = [&](int kt, int s) {
        uint32_t da = sbase + (uint32_t)((s * STILE_F + r0 * SROW + kc) * 4);
        uint32_t db = da + (uint32_t)(ATILE_F * 4);
        const float* ga = ga0 + kt * BK;
        const float* gb = gb0 + kt * BK;
        #pragma unroll
        for (int i = 0; i < 8; i++) {
            cp_async16(da + i * 16 * SROW * 4, ga + (size_t)i * 16 * DM_);
            cp_async16(db + i * 16 * SROW * 4, gb + (size_t)i * 16 * DM_);
        }
    };

    load_tile(0, 0); CP_COMMIT();
    load_tile(1, 1); CP_COMMIT();

    int stage = 0;
    for (int kt = 0; kt < NKT; kt++) {
        CP_WAIT1();
        __syncthreads();
        if (kt + 2 < NKT) load_tile(kt + 2, (kt + 2) % STG);
        CP_COMMIT();

        const float* as = sm + (size_t)stage * STILE_F;
        const float* ws = as + ATILE_F;
        #pragma unroll
        for (int ks = 0; ks < 4; ks++) {
            const int kk = ks * 8;
            uint32_t af[4][4];
            #pragma unroll
            for (int mt = 0; mt < 4; mt++) {
                const int row = wm * 64 + mt * 16 + gid;
                af[mt][0] = __float_as_uint(as[row * SROW + kk + tg]);
                af[mt][1] = __float_as_uint(as[(row + 8) * SROW + kk + tg]);
                af[mt][2] = __float_as_uint(as[row * SROW + kk + 4 + tg]);
                af[mt][3] = __float_as_uint(as[(row + 8) * SROW + kk + 4 + tg]);
            }
            #pragma unroll
            for (int nt = 0; nt < 8; nt++) {
                const int cb = wn * 64 + nt * 8 + gid;
                uint32_t b0 = __float_as_uint(ws[cb * SROW + kk + tg]);
                uint32_t b1 = __float_as_uint(ws[cb * SROW + kk + 4 + tg]);
                #pragma unroll
                for (int mt = 0; mt < 4; mt++)
                    mma_tf32(acc[mt][nt],
                             af[mt][0], af[mt][1], af[mt][2], af[mt][3], b0, b1);
            }
        }
        stage = (stage + 1 == STG) ? 0 : stage + 1;
    }

    // ---- store C ----
    #pragma unroll
    for (int mt = 0; mt < 4; mt++) {
        const int row0 = bm + wm * 64 + mt * 16 + gid;
        #pragma unroll
        for (int nt = 0; nt < 8; nt++) {
            const int col0 = bn + wn * 64 + nt * 8 + tg * 2;
            *(float2*)(C + (size_t)row0 * DM_ + col0) =
                make_float2(acc[mt][nt][0], acc[mt][nt][1]);
            *(float2*)(C + (size_t)(row0 + 8) * DM_ + col0) =
                make_float2(acc[mt][nt][2], acc[mt][nt][3]);
        }
    }
}

// ---------------- mask dtype detection -------------------------------------
__global__ void detect_mask_kernel(const unsigned char* __restrict__ m) {
    __shared__ int f0, f1;
    if (threadIdx.x == 0) { f0 = 0; f1 = 0; }
    __syncthreads();
    int lf = 0, lb = 0;
    for (int i = threadIdx.x; i < 4096; i += blockDim.x) {
        unsigned char c = m[i];
        if (c == 0x3Fu || c == 0x80u) lf = 1;
        if (c != 0u && (i & 3) != 0) lb = 1;
    }
    if (lf) atomicOr(&f0, 1);
    if (lb) atomicOr(&f1, 1);
    __syncthreads();
    if (threadIdx.x == 0) g_maskmode = f0 ? 2 : (f1 ? 0 : 1);
}

__device__ __forceinline__ bool load_mask(const void* m, int mode, size_t idx) {
    if (mode == 2) return ((const float*)m)[idx] != 0.0f;
    if (mode == 1) return ((const int*)m)[idx] != 0;
    return ((const unsigned char*)m)[idx] != 0u;
}

// ---------------- effective map weights ------------------------------------
__global__ void weff_kernel(const float* __restrict__ Wq,
                            const float* __restrict__ Wk,
                            const float* __restrict__ Wmap) {
    int t = blockIdx.x * blockDim.x + threadIdx.x;
    if (t >= 2 * H_ * DM_) return;
    int isK = t >= H_ * DM_;
    int r = isK ? (t - H_ * DM_) : t;
    int h = r / DM_, dm = r % DM_;
    const float* W  = isK ? Wk : Wq;
    const float* wm = Wmap + (isK ? DK_ : 0);
    float s = 0.f;
    #pragma unroll 8
    for (int d = 0; d < DK_; d++)
        s += wm[d] * W[(size_t)(h * DK_ + d) * DM_ + dm];
    if (isK) g_wkeff[r] = s; else g_wqeff[r] = s;
}

// ---------------- fused scores + softmax + attn write ----------------------
__global__ __launch_bounds__(256) void attn_kernel(
    const float* __restrict__ qin, const float* __restrict__ kin,
    const void* __restrict__ mask, float* __restrict__ attn_out, int write_out)
{
    __shared__ float wS[2 * H_ * DM_];
    __shared__ float sqS[H_ * LQ_];
    __shared__ float skS[H_ * LK_];
    const int b = blockIdx.x;
    const int tid = threadIdx.x, warp = tid >> 5, lane = tid & 31;

    for (int i = tid; i < H_ * DM_; i += 256) {
        wS[i]            = g_wqeff[i];
        wS[H_ * DM_ + i] = g_wkeff[i];
    }
    __syncthreads();

    for (int j = warp; j < LQ_ + LK_; j += 8) {
        const float* vec;
        const float* wf;
        if (j < LQ_) { vec = qin + ((size_t)b * LQ_ + j) * DM_;         wf = wS; }
        else         { vec = kin + ((size_t)b * LK_ + (j - LQ_)) * DM_; wf = wS + H_ * DM_; }
        float s0 = 0.f, s1 = 0.f, s2 = 0.f, s3 = 0.f;
        for (int idx = lane; idx < DM_; idx += 32) {
            float x = vec[idx];
            s0 += x * wf[idx];
            s1 += x * wf[DM_ + idx];
            s2 += x * wf[2 * DM_ + idx];
            s3 += x * wf[3 * DM_ + idx];
        }
        #pragma unroll
        for (int o = 16; o; o >>= 1) {
            s0 += __shfl_xor_sync(0xffffffffu, s0, o);
            s1 += __shfl_xor_sync(0xffffffffu, s1, o);
            s2 += __shfl_xor_sync(0xffffffffu, s2, o);
            s3 += __shfl_xor_sync(0xffffffffu, s3, o);
        }
        if (lane == 0) {
            if (j < LQ_) {
                sqS[0 * LQ_ + j] = s0; sqS[1 * LQ_ + j] = s1;
                sqS[2 * LQ_ + j] = s2; sqS[3 * LQ_ + j] = s3;
            } else {
                int kk = j - LQ_;
                skS[0 * LK_ + kk] = s0; skS[1 * LK_ + kk] = s1;
                skS[2 * LK_ + kk] = s2; skS[3 * LK_ + kk] = s3;
            }
        }
    }
    __syncthreads();

    const int mm = g_maskmode;
    for (int r = warp; r < H_ * LQ_; r += 8) {
        const int h = r >> 5, qq = r & 31;
        const float sq = sqS[r];
        const size_t mbase = ((size_t)b * LQ_ + qq) * LK_;
        bool m0 = load_mask(mask, mm, mbase + lane);
        bool m1 = load_mask(mask, mm, mbase + lane + 32);
        float v0 = m0 ? -1e10f : sq + skS[h * LK_ + lane];
        float v1 = m1 ? -1e10f : sq + skS[h * LK_ + lane + 32];
        float mx = fmaxf(v0, v1);
        #pragma unroll
        for (int o = 16; o; o >>= 1) mx = fmaxf(mx, __shfl_xor_sync(0xffffffffu, mx, o));
        float p0 = expf(v0 - mx), p1 = expf(v1 - mx);
        float sm = p0 + p1;
        #pragma unroll
        for (int o = 16; o; o >>= 1) sm += __shfl_xor_sync(0xffffffffu, sm, o);
        float inv = 1.0f / sm;
        p0 *= inv; p1 *= inv;
        const size_t ob = (((size_t)h * B_ + b) * LQ_ + qq) * LK_;
        g_attn[ob + lane]      = p0;
        g_attn[ob + lane + 32] = p1;
        if (write_out) {
            attn_out[ob + lane]      = p0;
            attn_out[ob + lane + 32] = p1;
        }
    }
}

// ---------------- attn @ vp  -> g_oattn -------------------------------------
__global__ __launch_bounds__(256) void av_kernel() {
    const int b = blockIdx.x;
    __shared__ float aS[H_ * LQ_ * LK_];
    for (int i = threadIdx.x; i < H_ * LQ_ * LK_; i += 256) {
        int h = i >> 11;
        int rem = i & 2047;
        aS[i] = g_attn[(((size_t)h * B_ + b) * LQ_) * LK_ + rem];
    }
    __syncthreads();
    #pragma unroll
    for (int c0 = 0; c0 < 2; c0++) {
        const int col = threadIdx.x + c0 * 256;
        const int h = col >> 7;
        float acc[LQ_];
        #pragma unroll
        for (int q = 0; q < LQ_; q++) acc[q] = 0.f;
        const float* vpb = g_vp + (size_t)b * LK_ * DM_ + col;
        const float* aH = aS + h * LQ_ * LK_;
        for (int kk = 0; kk < LK_; kk++) {
            float vv = vpb[(size_t)kk * DM_];
            #pragma unroll
            for (int q = 0; q < LQ_; q++) acc[q] += aH[q * LK_ + kk] * vv;
        }
        #pragma unroll
        for (int q = 0; q < LQ_; q++)
            g_oattn[((size_t)b * LQ_ + q) * DM_ + col] = acc[q];
    }
}

// ---------------- bias + leakyReLU + residual + LayerNorm ------------------
__global__ __launch_bounds__(128) void epilogue_kernel(
    const float* __restrict__ qin, const float* __restrict__ fcb,
    const float* __restrict__ gamma, const float* __restrict__ beta,
    float* __restrict__ out)
{
    const int row = blockIdx.x;
    const int tid = threadIdx.x;
    __shared__ float rs[8];
    float y[4];
    float s = 0.f, s2 = 0.f;
    #pragma unroll
    for (int i = 0; i < 4; i++) {
        int j = tid + i * 128;
        float x = g_fcout[(size_t)row * DM_ + j] + fcb[j];
        x = (x >= 0.f) ? x : 0.2f * x;
        x += qin[(size_t)row * DM_ + j];
        y[i] = x; s += x; s2 += x * x;
    }
    #pragma unroll
    for (int o = 16; o; o >>= 1) {
        s  += __shfl_xor_sync(0xffffffffu, s, o);
        s2 += __shfl_xor_sync(0xffffffffu, s2, o);
    }
    const int warp = tid >> 5, lane = tid & 31;
    if (lane == 0) { rs[warp] = s; rs[4 + warp] = s2; }
    __syncthreads();
    s  = rs[0] + rs[1] + rs[2] + rs[3];
    s2 = rs[4] + rs[5] + rs[6] + rs[7];
    const float mu  = s * (1.0f / DM_);
    const float var = s2 * (1.0f / DM_) - mu * mu;
    const float inv = rsqrtf(var + 1e-5f);
    #pragma unroll
    for (int i = 0; i < 4; i++) {
        int j = tid + i * 128;
        out[(size_t)row * DM_ + j] = gamma[j] * (y[i] - mu) * inv + beta[j];
    }
}

// ---------------- launch ----------------------------------------------------
extern "C" void kernel_launch(void* const* d_in, const int* in_sizes, int n_in,
                              void* d_out, int out_size)
{
    const float* q    = (const float*)d_in[0];
    const float* k    = (const float*)d_in[1];
    const float* v    = (const float*)d_in[2];
    const void*  mask =               d_in[3];
    const float* Wq   = (const float*)d_in[4];
    const float* Wk   = (const float*)d_in[5];
    const float* Wv   = (const float*)d_in[6];
    const float* Wmap = (const float*)d_in[7];
    const float* fcW  = (const float*)d_in[8];
    const float* fcb  = (const float*)d_in[9];
    const float* gma  = (const float*)d_in[10];
    const float* bta  = (const float*)d_in[11];
    float* out = (float*)d_out;

    const size_t out_elems  = (size_t)B_ * LQ_ * DM_;
    const size_t attn_elems = (size_t)H_ * B_ * LQ_ * LK_;
    int write_attn = ((size_t)out_size >= out_elems + attn_elems) ? 1 : 0;
    float* attn_out = out + out_elems;

    void *p_vp = nullptr, *p_oattn = nullptr, *p_fcout = nullptr;
    cudaGetSymbolAddress(&p_vp, g_vp);
    cudaGetSymbolAddress(&p_oattn, g_oattn);
    cudaGetSymbolAddress(&p_fcout, g_fcout);

    cudaFuncSetAttribute(tmma_tf32, cudaFuncAttributeMaxDynamicSharedMemorySize,
                         GEMM_SMEM_BYTES);

    detect_mask_kernel<<<1, 256>>>((const unsigned char*)mask);
    weff_kernel<<<(2 * H_ * DM_ + 255) / 256, 256>>>(Wq, Wk, Wmap);
    attn_kernel<<<B_, 256>>>(q, k, mask, attn_out, write_attn);

    // vp = v @ Wv^T : M = 65536, N = 512, K = 512
    {
        dim3 grid(DM_ / BN, (B_ * LK_) / BM);
        tmma_tf32<<<grid, 128, GEMM_SMEM_BYTES>>>(v, Wv, (float*)p_vp);
    }

    av_kernel<<<B_, 256>>>();

    // fc = oattn @ fcW^T : M = 32768, N = 512, K = 512
    {
        dim3 grid(DM_ / BN, (B_ * LQ_) / BM);
        tmma_tf32<<<grid, 128, GEMM_SMEM_BYTES>>>((const float*)p_oattn, fcW, (float*)p_fcout);
    }

    epilogue_kernel<<<B_ * LQ_, 128>>>(q, fcb, gma, bta, out);
}

// round 5
// speedup vs baseline: 2.5472x; 1.1049x over previous
#include <cuda_runtime.h>
#include <cuda_fp16.h>
#include <cstdint>
#include <cstddef>

// Problem constants
#define H_    4
#define DM_   512
#define DK_   128
#define B_    1024
#define LQ_   32
#define LK_   64

// ---------------- scratch (device globals; no allocation allowed) ----------
__device__ float g_wqeff[H_ * DM_];
__device__ float g_wkeff[H_ * DM_];
__device__ float g_attn[(size_t)H_ * B_ * LQ_ * LK_];            //  33 MB
__device__ __align__(16) __half g_vh[(size_t)B_ * LK_ * DM_];    //  67 MB (v fp16)
__device__ __align__(16) __half g_wvh[DM_ * DM_];                // 0.5 MB
__device__ __align__(16) __half g_fcwh[DM_ * DM_];               // 0.5 MB
__device__ __align__(16) __half g_vph[(size_t)B_ * LK_ * DM_];   //  67 MB (vp fp16)
__device__ __align__(16) __half g_oh[(size_t)B_ * LQ_ * DM_];    //  33 MB (oattn fp16)
__device__ float g_fcout[(size_t)B_ * LQ_ * DM_];                //  67 MB
__device__ int   g_maskmode;

__device__ __forceinline__ uint32_t smem_u32(const void* p) {
    uint32_t a;
    asm("{ .reg .u64 t; cvta.to.shared.u64 t, %1; cvt.u32.u64 %0, t; }"
        : "=r"(a) : "l"(p));
    return a;
}
__device__ __forceinline__ void cp_async16(uint32_t dst, const void* src) {
    asm volatile("cp.async.cg.shared.global [%0], [%1], 16;" :: "r"(dst), "l"(src));
}
#define CP_COMMIT() asm volatile("cp.async.commit_group;" ::: "memory")
#define CP_WAIT1()  asm volatile("cp.async.wait_group 1;" ::: "memory")

__device__ __forceinline__ void ldsm_x4(uint32_t& r0, uint32_t& r1, uint32_t& r2,
                                        uint32_t& r3, uint32_t addr) {
    asm volatile("ldmatrix.sync.aligned.m8n8.x4.shared.b16 {%0,%1,%2,%3}, [%4];"
                 : "=r"(r0), "=r"(r1), "=r"(r2), "=r"(r3) : "r"(addr));
}
__device__ __forceinline__ void mma_f16(float* c,
                                        uint32_t a0, uint32_t a1, uint32_t a2, uint32_t a3,
                                        uint32_t b0, uint32_t b1) {
    asm volatile("mma.sync.aligned.m16n8k16.row.col.f32.f16.f16.f32 "
                 "{%0,%1,%2,%3}, {%4,%5,%6,%7}, {%8,%9}, {%0,%1,%2,%3};"
                 : "+f"(c[0]), "+f"(c[1]), "+f"(c[2]), "+f"(c[3])
                 : "r"(a0), "r"(a1), "r"(a2), "r"(a3), "r"(b0), "r"(b1));
}

__device__ __forceinline__ void store2(float* C, size_t idx, float x, float y) {
    *(float2*)(C + idx) = make_float2(x, y);
}
__device__ __forceinline__ void store2(__half* C, size_t idx, float x, float y) {
    *(__half2*)(C + idx) = __floats2half2_rn(x, y);
}

// ====================== fp16 mma GEMM:  C = A * W^T =========================
// A[M,512] fp16 row-major, W[512,512] fp16 row-major ([N,K] == col-layout B).
// CTA 128x128, K-tile 32, 4 warps (2m x 2n), warp tile 64x64.
// cp.async 3-stage; smem rows stride 40 halfs (80B) -> ldmatrix conflict-free.
#define BM 128
#define BN 128
#define BK 32
#define NKT (DM_ / BK)        // 16
#define STG 3
#define SROWH 40              // halfs per smem row (80 bytes)
#define STG_BYTES (2 * BM * SROWH * 2)      // A+B per stage = 20480 B
#define GEMM_SMEM (STG * STG_BYTES)         // 61440 B

template <typename OutT>
__global__ void __launch_bounds__(128, 2) hgemm(
    const __half* __restrict__ A, const __half* __restrict__ W,
    OutT* __restrict__ C)
{
    extern __shared__ __half smh[];
    const uint32_t sbase = smem_u32(smh);
    const int tid = threadIdx.x;
    const int wid = tid >> 5, lane = tid & 31;
    const int gid = lane >> 2, tg = lane & 3;
    const int wm = wid >> 1, wn = wid & 1;
    const int bm = blockIdx.y * BM;
    const int bn = blockIdx.x * BN;

    float acc[4][8][4];
    #pragma unroll
    for (int i = 0; i < 4; i++)
        #pragma unroll
        for (int j = 0; j < 8; j++)
            #pragma unroll
            for (int r = 0; r < 4; r++) acc[i][j][r] = 0.f;

    // loader: thread = one row of A tile and one row of B tile (64B each)
    const __half* ga0 = A + (size_t)(bm + tid) * DM_;
    const __half* gb0 = W + (size_t)(bn + tid) * DM_;

    auto load_tile = [&](int kt, int s) {
        uint32_t da = sbase + (uint32_t)(s * STG_BYTES) + (uint32_t)tid * (SROWH * 2);
        uint32_t db = da + BM * SROWH * 2;
        const __half* ga = ga0 + kt * BK;
        const __half* gb = gb0 + kt * BK;
        #pragma unroll
        for (int c = 0; c < 4; c++) {
            cp_async16(da + c * 16, ga + c * 8);
            cp_async16(db + c * 16, gb + c * 8);
        }
    };

    // ldmatrix lane addressing (bytes within stage)
    const uint32_t aOff = (uint32_t)(wm * 64 + (lane & 15)) * (SROWH * 2)
                        + (uint32_t)(lane >> 4) * 16;
    const uint32_t bOff = (uint32_t)(BM * SROWH * 2)
                        + (uint32_t)(wn * 64 + (lane & 7) + ((lane >> 4) << 3)) * (SROWH * 2)
                        + (uint32_t)((lane >> 3) & 1) * 16;

    load_tile(0, 0); CP_COMMIT();
    load_tile(1, 1); CP_COMMIT();

    int stage = 0;
    for (int kt = 0; kt < NKT; kt++) {
        CP_WAIT1();
        __syncthreads();
        if (kt + 2 < NKT) load_tile(kt + 2, (kt + 2) % STG);
        CP_COMMIT();

        const uint32_t sa = sbase + (uint32_t)(stage * STG_BYTES);
        #pragma unroll
        for (int ks = 0; ks < 2; ks++) {
            uint32_t af[4][4];
            #pragma unroll
            for (int mt = 0; mt < 4; mt++)
                ldsm_x4(af[mt][0], af[mt][1], af[mt][2], af[mt][3],
                        sa + aOff + (uint32_t)(mt * 16 * SROWH * 2) + (uint32_t)(ks * 32));
            #pragma unroll
            for (int ntp = 0; ntp < 4; ntp++) {
                uint32_t b0, b1, b2, b3;
                ldsm_x4(b0, b1, b2, b3,
                        sa + bOff + (uint32_t)(ntp * 16 * SROWH * 2) + (uint32_t)(ks * 32));
                #pragma unroll
                for (int mt = 0; mt < 4; mt++) {
                    mma_f16(acc[mt][2 * ntp],     af[mt][0], af[mt][1], af[mt][2], af[mt][3], b0, b1);
                    mma_f16(acc[mt][2 * ntp + 1], af[mt][0], af[mt][1], af[mt][2], af[mt][3], b2, b3);
                }
            }
        }
        stage = (stage + 1 == STG) ? 0 : stage + 1;
    }

    // ---- store C ----
    #pragma unroll
    for (int mt = 0; mt < 4; mt++) {
        const int row0 = bm + wm * 64 + mt * 16 + gid;
        #pragma unroll
        for (int nt = 0; nt < 8; nt++) {
            const int col0 = bn + wn * 64 + nt * 8 + tg * 2;
            store2(C, (size_t)row0 * DM_ + col0,       acc[mt][nt][0], acc[mt][nt][1]);
            store2(C, (size_t)(row0 + 8) * DM_ + col0, acc[mt][nt][2], acc[mt][nt][3]);
        }
    }
}

// ---------------- fp32 -> fp16 converters -----------------------------------
__global__ void conv_f2h_kernel(const float* __restrict__ src,
                                __half* __restrict__ dst, size_t n) {
    size_t i = ((size_t)blockIdx.x * blockDim.x + threadIdx.x) * 8;
    if (i >= n) return;
    float4 f0 = *(const float4*)(src + i);
    float4 f1 = *(const float4*)(src + i + 4);
    __half2 h[4];
    h[0] = __floats2half2_rn(f0.x, f0.y);
    h[1] = __floats2half2_rn(f0.z, f0.w);
    h[2] = __floats2half2_rn(f1.x, f1.y);
    h[3] = __floats2half2_rn(f1.z, f1.w);
    *(uint4*)(dst + i) = *(uint4*)h;
}

// ---------------- mask dtype detection -------------------------------------
__global__ void detect_mask_kernel(const unsigned char* __restrict__ m) {
    __shared__ int f0, f1;
    if (threadIdx.x == 0) { f0 = 0; f1 = 0; }
    __syncthreads();
    int lf = 0, lb = 0;
    for (int i = threadIdx.x; i < 4096; i += blockDim.x) {
        unsigned char c = m[i];
        if (c == 0x3Fu || c == 0x80u) lf = 1;
        if (c != 0u && (i & 3) != 0) lb = 1;
    }
    if (lf) atomicOr(&f0, 1);
    if (lb) atomicOr(&f1, 1);
    __syncthreads();
    if (threadIdx.x == 0) g_maskmode = f0 ? 2 : (f1 ? 0 : 1);
}

__device__ __forceinline__ bool load_mask(const void* m, int mode, size_t idx) {
    if (mode == 2) return ((const float*)m)[idx] != 0.0f;
    if (mode == 1) return ((const int*)m)[idx] != 0;
    return ((const unsigned char*)m)[idx] != 0u;
}

// ---------------- effective map weights ------------------------------------
__global__ void weff_kernel(const float* __restrict__ Wq,
                            const float* __restrict__ Wk,
                            const float* __restrict__ Wmap) {
    int t = blockIdx.x * blockDim.x + threadIdx.x;
    if (t >= 2 * H_ * DM_) return;
    int isK = t >= H_ * DM_;
    int r = isK ? (t - H_ * DM_) : t;
    int h = r / DM_, dm = r % DM_;
    const float* W  = isK ? Wk : Wq;
    const float* wm = Wmap + (isK ? DK_ : 0);
    float s = 0.f;
    #pragma unroll 8
    for (int d = 0; d < DK_; d++)
        s += wm[d] * W[(size_t)(h * DK_ + d) * DM_ + dm];
    if (isK) g_wkeff[r] = s; else g_wqeff[r] = s;
}

// ---------------- fused scores + softmax + attn write ----------------------
__global__ __launch_bounds__(256) void attn_kernel(
    const float* __restrict__ qin, const float* __restrict__ kin,
    const void* __restrict__ mask, float* __restrict__ attn_out, int write_out)
{
    __shared__ float wS[2 * H_ * DM_];
    __shared__ float sqS[H_ * LQ_];
    __shared__ float skS[H_ * LK_];
    const int b = blockIdx.x;
    const int tid = threadIdx.x, warp = tid >> 5, lane = tid & 31;

    for (int i = tid; i < H_ * DM_; i += 256) {
        wS[i]            = g_wqeff[i];
        wS[H_ * DM_ + i] = g_wkeff[i];
    }
    __syncthreads();

    for (int j = warp; j < LQ_ + LK_; j += 8) {
        const float* vec;
        const float* wf;
        if (j < LQ_) { vec = qin + ((size_t)b * LQ_ + j) * DM_;         wf = wS; }
        else         { vec = kin + ((size_t)b * LK_ + (j - LQ_)) * DM_; wf = wS + H_ * DM_; }
        float s0 = 0.f, s1 = 0.f, s2 = 0.f, s3 = 0.f;
        for (int idx = lane; idx < DM_; idx += 32) {
            float x = vec[idx];
            s0 += x * wf[idx];
            s1 += x * wf[DM_ + idx];
            s2 += x * wf[2 * DM_ + idx];
            s3 += x * wf[3 * DM_ + idx];
        }
        #pragma unroll
        for (int o = 16; o; o >>= 1) {
            s0 += __shfl_xor_sync(0xffffffffu, s0, o);
            s1 += __shfl_xor_sync(0xffffffffu, s1, o);
            s2 += __shfl_xor_sync(0xffffffffu, s2, o);
            s3 += __shfl_xor_sync(0xffffffffu, s3, o);
        }
        if (lane == 0) {
            if (j < LQ_) {
                sqS[0 * LQ_ + j] = s0; sqS[1 * LQ_ + j] = s1;
                sqS[2 * LQ_ + j] = s2; sqS[3 * LQ_ + j] = s3;
            } else {
                int kk = j - LQ_;
                skS[0 * LK_ + kk] = s0; skS[1 * LK_ + kk] = s1;
                skS[2 * LK_ + kk] = s2; skS[3 * LK_ + kk] = s3;
            }
        }
    }
    __syncthreads();

    const int mm = g_maskmode;
    for (int r = warp; r < H_ * LQ_; r += 8) {
        const int h = r >> 5, qq = r & 31;
        const float sq = sqS[r];
        const size_t mbase = ((size_t)b * LQ_ + qq) * LK_;
        bool m0 = load_mask(mask, mm, mbase + lane);
        bool m1 = load_mask(mask, mm, mbase + lane + 32);
        float v0 = m0 ? -1e10f : sq + skS[h * LK_ + lane];
        float v1 = m1 ? -1e10f : sq + skS[h * LK_ + lane + 32];
        float mx = fmaxf(v0, v1);
        #pragma unroll
        for (int o = 16; o; o >>= 1) mx = fmaxf(mx, __shfl_xor_sync(0xffffffffu, mx, o));
        float p0 = expf(v0 - mx), p1 = expf(v1 - mx);
        float sm = p0 + p1;
        #pragma unroll
        for (int o = 16; o; o >>= 1) sm += __shfl_xor_sync(0xffffffffu, sm, o);
        float inv = 1.0f / sm;
        p0 *= inv; p1 *= inv;
        const size_t ob = (((size_t)h * B_ + b) * LQ_ + qq) * LK_;
        g_attn[ob + lane]      = p0;
        g_attn[ob + lane + 32] = p1;
        if (write_out) {
            attn_out[ob + lane]      = p0;
            attn_out[ob + lane + 32] = p1;
        }
    }
}

// ---------------- attn @ vp (fp16 vp) -> g_oh (fp16) ------------------------
__global__ __launch_bounds__(256) void av_kernel() {
    const int b = blockIdx.x;
    __shared__ float aS[H_ * LQ_ * LK_];
    for (int i = threadIdx.x; i < H_ * LQ_ * LK_; i += 256) {
        int h = i >> 11;
        int rem = i & 2047;
        aS[i] = g_attn[(((size_t)h * B_ + b) * LQ_) * LK_ + rem];
    }
    __syncthreads();
    #pragma unroll
    for (int c0 = 0; c0 < 2; c0++) {
        const int col = threadIdx.x + c0 * 256;
        const int h = col >> 7;
        float acc[LQ_];
        #pragma unroll
        for (int q = 0; q < LQ_; q++) acc[q] = 0.f;
        const __half* vpb = g_vph + (size_t)b * LK_ * DM_ + col;
        const float* aH = aS + h * LQ_ * LK_;
        for (int kk = 0; kk < LK_; kk++) {
            float vv = __half2float(vpb[(size_t)kk * DM_]);
            #pragma unroll
            for (int q = 0; q < LQ_; q++) acc[q] += aH[q * LK_ + kk] * vv;
        }
        #pragma unroll
        for (int q = 0; q < LQ_; q++)
            g_oh[((size_t)b * LQ_ + q) * DM_ + col] = __float2half_rn(acc[q]);
    }
}

// ---------------- bias + leakyReLU + residual + LayerNorm ------------------
__global__ __launch_bounds__(128) void epilogue_kernel(
    const float* __restrict__ qin, const float* __restrict__ fcb,
    const float* __restrict__ gamma, const float* __restrict__ beta,
    float* __restrict__ out)
{
    const int row = blockIdx.x;
    const int tid = threadIdx.x;
    __shared__ float rs[8];
    float y[4];
    float s = 0.f, s2 = 0.f;
    #pragma unroll
    for (int i = 0; i < 4; i++) {
        int j = tid + i * 128;
        float x = g_fcout[(size_t)row * DM_ + j] + fcb[j];
        x = (x >= 0.f) ? x : 0.2f * x;
        x += qin[(size_t)row * DM_ + j];
        y[i] = x; s += x; s2 += x * x;
    }
    #pragma unroll
    for (int o = 16; o; o >>= 1) {
        s  += __shfl_xor_sync(0xffffffffu, s, o);
        s2 += __shfl_xor_sync(0xffffffffu, s2, o);
    }
    const int warp = tid >> 5, lane = tid & 31;
    if (lane == 0) { rs[warp] = s; rs[4 + warp] = s2; }
    __syncthreads();
    s  = rs[0] + rs[1] + rs[2] + rs[3];
    s2 = rs[4] + rs[5] + rs[6] + rs[7];
    const float mu  = s * (1.0f / DM_);
    const float var = s2 * (1.0f / DM_) - mu * mu;
    const float inv = rsqrtf(var + 1e-5f);
    #pragma unroll
    for (int i = 0; i < 4; i++) {
        int j = tid + i * 128;
        out[(size_t)row * DM_ + j] = gamma[j] * (y[i] - mu) * inv + beta[j];
    }
}

// ---------------- launch ----------------------------------------------------
extern "C" void kernel_launch(void* const* d_in, const int* in_sizes, int n_in,
                              void* d_out, int out_size)
{
    const float* q    = (const float*)d_in[0];
    const float* k    = (const float*)d_in[1];
    const float* v    = (const float*)d_in[2];
    const void*  mask =               d_in[3];
    const float* Wq   = (const float*)d_in[4];
    const float* Wk   = (const float*)d_in[5];
    const float* Wv   = (const float*)d_in[6];
    const float* Wmap = (const float*)d_in[7];
    const float* fcW  = (const float*)d_in[8];
    const float* fcb  = (const float*)d_in[9];
    const float* gma  = (const float*)d_in[10];
    const float* bta  = (const float*)d_in[11];
    float* out = (float*)d_out;

    const size_t out_elems  = (size_t)B_ * LQ_ * DM_;
    const size_t attn_elems = (size_t)H_ * B_ * LQ_ * LK_;
    int write_attn = ((size_t)out_size >= out_elems + attn_elems) ? 1 : 0;
    float* attn_out = out + out_elems;

    void *p_vh = nullptr, *p_wvh = nullptr, *p_fcwh = nullptr;
    void *p_vph = nullptr, *p_oh = nullptr, *p_fcout = nullptr;
    cudaGetSymbolAddress(&p_vh, g_vh);
    cudaGetSymbolAddress(&p_wvh, g_wvh);
    cudaGetSymbolAddress(&p_fcwh, g_fcwh);
    cudaGetSymbolAddress(&p_vph, g_vph);
    cudaGetSymbolAddress(&p_oh, g_oh);
    cudaGetSymbolAddress(&p_fcout, g_fcout);

    cudaFuncSetAttribute(hgemm<__half>, cudaFuncAttributeMaxDynamicSharedMemorySize, GEMM_SMEM);
    cudaFuncSetAttribute(hgemm<float>,  cudaFuncAttributeMaxDynamicSharedMemorySize, GEMM_SMEM);

    detect_mask_kernel<<<1, 256>>>((const unsigned char*)mask);
    weff_kernel<<<(2 * H_ * DM_ + 255) / 256, 256>>>(Wq, Wk, Wmap);

    // convert v, Wv, fcW to fp16
    {
        size_t nv = (size_t)B_ * LK_ * DM_;                 // 33.5M
        conv_f2h_kernel<<<(unsigned)(nv / (256 * 8)), 256>>>(v, (__half*)p_vh, nv);
        size_t nw = (size_t)DM_ * DM_;                      // 262144
        conv_f2h_kernel<<<(unsigned)(nw / (256 * 8)), 256>>>(Wv, (__half*)p_wvh, nw);
        conv_f2h_kernel<<<(unsigned)(nw / (256 * 8)), 256>>>(fcW, (__half*)p_fcwh, nw);
    }

    attn_kernel<<<B_, 256>>>(q, k, mask, attn_out, write_attn);

    // vp = v @ Wv^T : M = 65536, N = 512, K = 512 (fp16 mma, fp16 out)
    {
        dim3 grid(DM_ / BN, (B_ * LK_) / BM);
        hgemm<__half><<<grid, 128, GEMM_SMEM>>>((const __half*)p_vh, (const __half*)p_wvh,
                                                (__half*)p_vph);
    }

    av_kernel<<<B_, 256>>>();

    // fc = oattn @ fcW^T : M = 32768, N = 512, K = 512 (fp16 mma, fp32 out)
    {
        dim3 grid(DM_ / BN, (B_ * LQ_) / BM);
        hgemm<float><<<grid, 128, GEMM_SMEM>>>((const __half*)p_oh, (const __half*)p_fcwh,
                                               (float*)p_fcout);
    }

    epilogue_kernel<<<B_ * LQ_, 128>>>(q, fcb, gma, bta, out);
}

// round 6
// speedup vs baseline: 3.5508x; 1.3940x over previous
#include <cuda_runtime.h>
#include <cuda_fp16.h>
#include <cstdint>
#include <cstddef>

// Problem constants
#define H_    4
#define DM_   512
#define DK_   128
#define B_    1024
#define LQ_   32
#define LK_   64

// ---------------- scratch (device globals; no allocation allowed) ----------
__device__ float g_wqeff[H_ * DM_];
__device__ float g_wkeff[H_ * DM_];
__device__ float g_attn[(size_t)H_ * B_ * LQ_ * LK_];            //  33 MB (fallback)
__device__ __align__(16) __half g_vh[(size_t)B_ * LK_ * DM_];    //  67 MB (v fp16)
__device__ __align__(16) __half g_wvh[DM_ * DM_];                // 0.5 MB
__device__ __align__(16) __half g_fcwh[DM_ * DM_];               // 0.5 MB
__device__ __align__(16) __half g_oh[(size_t)B_ * LQ_ * DM_];    //  33 MB (oattn fp16)
__device__ __align__(16) __half g_fch[(size_t)B_ * LQ_ * DM_];   //  33 MB (fc out fp16)
__device__ int   g_maskmode;

__device__ __forceinline__ uint32_t smem_u32(const void* p) {
    uint32_t a;
    asm("{ .reg .u64 t; cvta.to.shared.u64 t, %1; cvt.u32.u64 %0, t; }"
        : "=r"(a) : "l"(p));
    return a;
}
__device__ __forceinline__ void cp_async16(uint32_t dst, const void* src) {
    asm volatile("cp.async.cg.shared.global [%0], [%1], 16;" :: "r"(dst), "l"(src));
}
#define CP_COMMIT() asm volatile("cp.async.commit_group;" ::: "memory")
#define CP_WAIT1()  asm volatile("cp.async.wait_group 1;" ::: "memory")

__device__ __forceinline__ void ldsm_x4(uint32_t& r0, uint32_t& r1, uint32_t& r2,
                                        uint32_t& r3, uint32_t addr) {
    asm volatile("ldmatrix.sync.aligned.m8n8.x4.shared.b16 {%0,%1,%2,%3}, [%4];"
                 : "=r"(r0), "=r"(r1), "=r"(r2), "=r"(r3) : "r"(addr));
}
__device__ __forceinline__ void ldsm_x4_t(uint32_t& r0, uint32_t& r1, uint32_t& r2,
                                          uint32_t& r3, uint32_t addr) {
    asm volatile("ldmatrix.sync.aligned.m8n8.x4.trans.shared.b16 {%0,%1,%2,%3}, [%4];"
                 : "=r"(r0), "=r"(r1), "=r"(r2), "=r"(r3) : "r"(addr));
}
__device__ __forceinline__ void mma_f16(float* c,
                                        uint32_t a0, uint32_t a1, uint32_t a2, uint32_t a3,
                                        uint32_t b0, uint32_t b1) {
    asm volatile("mma.sync.aligned.m16n8k16.row.col.f32.f16.f16.f32 "
                 "{%0,%1,%2,%3}, {%4,%5,%6,%7}, {%8,%9}, {%0,%1,%2,%3};"
                 : "+f"(c[0]), "+f"(c[1]), "+f"(c[2]), "+f"(c[3])
                 : "r"(a0), "r"(a1), "r"(a2), "r"(a3), "r"(b0), "r"(b1));
}

// ====================== GEMM tiling constants ===============================
#define BM 128
#define BN 128
#define BK 32
#define NKT (DM_ / BK)        // 16
#define STG 3
#define SROWH 40              // halfs per smem row (80 bytes)
#define STG_BYTES (2 * BM * SROWH * 2)      // A+B per stage = 20480 B
#define GEMM_SMEM (STG * STG_BYTES)         // 61440 B
// O-phase smem layout (reuses stage memory after mainloop)
#define VPS 136               // vp_s stride in halfs
#define PS  72                // P_s stride in halfs
#define P_S_OFF (128 * VPS)   // halfs offset of P_s

// ============== fused GEMM1 + attnV:  vp = v@Wv^T;  O = P @ vp ==============
// CTA (bx, by): rows by*128 (= batches 2by, 2by+1), cols bx*128 (= head bx).
__global__ void __launch_bounds__(128, 2) hgemm_av(
    const __half* __restrict__ A, const __half* __restrict__ W,
    const float* __restrict__ attn_src, __half* __restrict__ O)
{
    extern __shared__ __half smh[];
    const uint32_t sbase = smem_u32(smh);
    const int tid = threadIdx.x;
    const int wid = tid >> 5, lane = tid & 31;
    const int gid = lane >> 2, tg = lane & 3;
    const int wm = wid >> 1, wn = wid & 1;
    const int bm = blockIdx.y * BM;
    const int bn = blockIdx.x * BN;

    float acc[4][8][4];
    #pragma unroll
    for (int i = 0; i < 4; i++)
        #pragma unroll
        for (int j = 0; j < 8; j++)
            #pragma unroll
            for (int r = 0; r < 4; r++) acc[i][j][r] = 0.f;

    const __half* ga0 = A + (size_t)(bm + tid) * DM_;
    const __half* gb0 = W + (size_t)(bn + tid) * DM_;

    auto load_tile = [&](int kt, int s) {
        uint32_t da = sbase + (uint32_t)(s * STG_BYTES) + (uint32_t)tid * (SROWH * 2);
        uint32_t db = da + BM * SROWH * 2;
        const __half* ga = ga0 + kt * BK;
        const __half* gb = gb0 + kt * BK;
        #pragma unroll
        for (int c = 0; c < 4; c++) {
            cp_async16(da + c * 16, ga + c * 8);
            cp_async16(db + c * 16, gb + c * 8);
        }
    };

    const uint32_t aOff = (uint32_t)(wm * 64 + (lane & 15)) * (SROWH * 2)
                        + (uint32_t)(lane >> 4) * 16;
    const uint32_t bOff = (uint32_t)(BM * SROWH * 2)
                        + (uint32_t)(wn * 64 + (lane & 7) + ((lane >> 4) << 3)) * (SROWH * 2)
                        + (uint32_t)((lane >> 3) & 1) * 16;

    load_tile(0, 0); CP_COMMIT();
    load_tile(1, 1); CP_COMMIT();

    int stage = 0;
    for (int kt = 0; kt < NKT; kt++) {
        CP_WAIT1();
        __syncthreads();
        if (kt + 2 < NKT) load_tile(kt + 2, (kt + 2) % STG);
        CP_COMMIT();

        const uint32_t sa = sbase + (uint32_t)(stage * STG_BYTES);
        #pragma unroll
        for (int ks = 0; ks < 2; ks++) {
            uint32_t af[4][4];
            #pragma unroll
            for (int mt = 0; mt < 4; mt++)
                ldsm_x4(af[mt][0], af[mt][1], af[mt][2], af[mt][3],
                        sa + aOff + (uint32_t)(mt * 16 * SROWH * 2) + (uint32_t)(ks * 32));
            #pragma unroll
            for (int ntp = 0; ntp < 4; ntp++) {
                uint32_t b0, b1, b2, b3;
                ldsm_x4(b0, b1, b2, b3,
                        sa + bOff + (uint32_t)(ntp * 16 * SROWH * 2) + (uint32_t)(ks * 32));
                #pragma unroll
                for (int mt = 0; mt < 4; mt++) {
                    mma_f16(acc[mt][2 * ntp],     af[mt][0], af[mt][1], af[mt][2], af[mt][3], b0, b1);
                    mma_f16(acc[mt][2 * ntp + 1], af[mt][0], af[mt][1], af[mt][2], af[mt][3], b2, b3);
                }
            }
        }
        stage = (stage + 1 == STG) ? 0 : stage + 1;
    }
    // ensure last cp.async groups retired before smem reuse
    asm volatile("cp.async.wait_group 0;" ::: "memory");
    __syncthreads();

    // ---- O phase: vp tile -> smem fp16; P (attn) -> smem fp16 --------------
    __half* vp_s = smh;             // [128][VPS]
    __half* P_s  = smh + P_S_OFF;   // [64][PS]  rows = b*32 + q, cols = k

    #pragma unroll
    for (int mt = 0; mt < 4; mt++) {
        const int row = wm * 64 + mt * 16 + gid;
        #pragma unroll
        for (int nt = 0; nt < 8; nt++) {
            const int col = wn * 64 + nt * 8 + tg * 2;
            *(__half2*)(vp_s + row * VPS + col) =
                __floats2half2_rn(acc[mt][nt][0], acc[mt][nt][1]);
            *(__half2*)(vp_s + (row + 8) * VPS + col) =
                __floats2half2_rn(acc[mt][nt][2], acc[mt][nt][3]);
        }
    }

    // load attn: 2 batches x 32 q x 64 k, fp32 -> fp16
    {
        const int prow = tid >> 1;            // 0..63  (b*32+q)
        const int pb   = prow >> 5;
        const int pq   = prow & 31;
        const int cb   = (tid & 1) * 32;
        const float* src = attn_src
            + ((((size_t)blockIdx.x * B_ + (2 * blockIdx.y + pb)) * LQ_ + pq) * LK_) + cb;
        #pragma unroll
        for (int j = 0; j < 8; j++) {
            float4 f = *(const float4*)(src + j * 4);
            *(__half2*)(P_s + prow * PS + cb + j * 4)     = __floats2half2_rn(f.x, f.y);
            *(__half2*)(P_s + prow * PS + cb + j * 4 + 2) = __floats2half2_rn(f.z, f.w);
        }
    }
    __syncthreads();

    // ---- O = P_b(32x64) @ vp_b(64x128); warp: batch = wid>>1, colhalf = wid&1
    const int wb = wid >> 1;         // batch within CTA
    const int wc = wid & 1;          // column half (64 cols)
    float oac[2][8][4];
    #pragma unroll
    for (int i = 0; i < 2; i++)
        #pragma unroll
        for (int j = 0; j < 8; j++)
            #pragma unroll
            for (int r = 0; r < 4; r++) oac[i][j][r] = 0.f;

    const uint32_t pbase  = sbase + (uint32_t)(P_S_OFF * 2);
    const uint32_t aOff2  = pbase
        + (uint32_t)(wb * 32 + (lane & 15)) * (PS * 2) + (uint32_t)(lane >> 4) * 16;
    const uint32_t bRow2  = (uint32_t)((lane & 7) + ((lane >> 3) & 1) * 8);
    const uint32_t bOff2  = sbase
        + (uint32_t)(wb * 64 + bRow2) * (VPS * 2)
        + (uint32_t)(wc * 64 + (lane >> 4) * 8) * 2;

    #pragma unroll
    for (int ks = 0; ks < 4; ks++) {
        uint32_t af[2][4];
        #pragma unroll
        for (int mt = 0; mt < 2; mt++)
            ldsm_x4(af[mt][0], af[mt][1], af[mt][2], af[mt][3],
                    aOff2 + (uint32_t)(mt * 16 * PS * 2) + (uint32_t)(ks * 32));
        #pragma unroll
        for (int ntp = 0; ntp < 4; ntp++) {
            uint32_t b0, b1, b2, b3;
            ldsm_x4_t(b0, b1, b2, b3,
                      bOff2 + (uint32_t)(ks * 16 * VPS * 2) + (uint32_t)(ntp * 16 * 2));
            #pragma unroll
            for (int mt = 0; mt < 2; mt++) {
                mma_f16(oac[mt][2 * ntp],     af[mt][0], af[mt][1], af[mt][2], af[mt][3], b0, b1);
                mma_f16(oac[mt][2 * ntp + 1], af[mt][0], af[mt][1], af[mt][2], af[mt][3], b2, b3);
            }
        }
    }

    // store O: row = (2*by + wb)*32 + q, col = bx*128 + wc*64 + nt*8 + tg*2
    {
        const size_t rb = ((size_t)(2 * blockIdx.y + wb)) * LQ_;
        #pragma unroll
        for (int mt = 0; mt < 2; mt++) {
            const int q0 = mt * 16 + gid;
            #pragma unroll
            for (int nt = 0; nt < 8; nt++) {
                const int col = blockIdx.x * BN + wc * 64 + nt * 8 + tg * 2;
                *(__half2*)(O + (rb + q0) * DM_ + col) =
                    __floats2half2_rn(oac[mt][nt][0], oac[mt][nt][1]);
                *(__half2*)(O + (rb + q0 + 8) * DM_ + col) =
                    __floats2half2_rn(oac[mt][nt][2], oac[mt][nt][3]);
            }
        }
    }
}

// ====================== plain fp16 GEMM (GEMM2) ==============================
template <typename OutT>
__global__ void __launch_bounds__(128, 2) hgemm(
    const __half* __restrict__ A, const __half* __restrict__ W,
    OutT* __restrict__ C)
{
    extern __shared__ __half smh[];
    const uint32_t sbase = smem_u32(smh);
    const int tid = threadIdx.x;
    const int wid = tid >> 5, lane = tid & 31;
    const int gid = lane >> 2, tg = lane & 3;
    const int wm = wid >> 1, wn = wid & 1;
    const int bm = blockIdx.y * BM;
    const int bn = blockIdx.x * BN;

    float acc[4][8][4];
    #pragma unroll
    for (int i = 0; i < 4; i++)
        #pragma unroll
        for (int j = 0; j < 8; j++)
            #pragma unroll
            for (int r = 0; r < 4; r++) acc[i][j][r] = 0.f;

    const __half* ga0 = A + (size_t)(bm + tid) * DM_;
    const __half* gb0 = W + (size_t)(bn + tid) * DM_;

    auto load_tile = [&](int kt, int s) {
        uint32_t da = sbase + (uint32_t)(s * STG_BYTES) + (uint32_t)tid * (SROWH * 2);
        uint32_t db = da + BM * SROWH * 2;
        const __half* ga = ga0 + kt * BK;
        const __half* gb = gb0 + kt * BK;
        #pragma unroll
        for (int c = 0; c < 4; c++) {
            cp_async16(da + c * 16, ga + c * 8);
            cp_async16(db + c * 16, gb + c * 8);
        }
    };

    const uint32_t aOff = (uint32_t)(wm * 64 + (lane & 15)) * (SROWH * 2)
                        + (uint32_t)(lane >> 4) * 16;
    const uint32_t bOff = (uint32_t)(BM * SROWH * 2)
                        + (uint32_t)(wn * 64 + (lane & 7) + ((lane >> 4) << 3)) * (SROWH * 2)
                        + (uint32_t)((lane >> 3) & 1) * 16;

    load_tile(0, 0); CP_COMMIT();
    load_tile(1, 1); CP_COMMIT();

    int stage = 0;
    for (int kt = 0; kt < NKT; kt++) {
        CP_WAIT1();
        __syncthreads();
        if (kt + 2 < NKT) load_tile(kt + 2, (kt + 2) % STG);
        CP_COMMIT();

        const uint32_t sa = sbase + (uint32_t)(stage * STG_BYTES);
        #pragma unroll
        for (int ks = 0; ks < 2; ks++) {
            uint32_t af[4][4];
            #pragma unroll
            for (int mt = 0; mt < 4; mt++)
                ldsm_x4(af[mt][0], af[mt][1], af[mt][2], af[mt][3],
                        sa + aOff + (uint32_t)(mt * 16 * SROWH * 2) + (uint32_t)(ks * 32));
            #pragma unroll
            for (int ntp = 0; ntp < 4; ntp++) {
                uint32_t b0, b1, b2, b3;
                ldsm_x4(b0, b1, b2, b3,
                        sa + bOff + (uint32_t)(ntp * 16 * SROWH * 2) + (uint32_t)(ks * 32));
                #pragma unroll
                for (int mt = 0; mt < 4; mt++) {
                    mma_f16(acc[mt][2 * ntp],     af[mt][0], af[mt][1], af[mt][2], af[mt][3], b0, b1);
                    mma_f16(acc[mt][2 * ntp + 1], af[mt][0], af[mt][1], af[mt][2], af[mt][3], b2, b3);
                }
            }
        }
        stage = (stage + 1 == STG) ? 0 : stage + 1;
    }

    #pragma unroll
    for (int mt = 0; mt < 4; mt++) {
        const int row0 = bm + wm * 64 + mt * 16 + gid;
        #pragma unroll
        for (int nt = 0; nt < 8; nt++) {
            const int col0 = bn + wn * 64 + nt * 8 + tg * 2;
            *(__half2*)(C + (size_t)row0 * DM_ + col0) =
                __floats2half2_rn(acc[mt][nt][0], acc[mt][nt][1]);
            *(__half2*)(C + (size_t)(row0 + 8) * DM_ + col0) =
                __floats2half2_rn(acc[mt][nt][2], acc[mt][nt][3]);
        }
    }
}

// ---------------- fp32 -> fp16 converters -----------------------------------
__global__ void conv_f2h_kernel(const float* __restrict__ src,
                                __half* __restrict__ dst, size_t n) {
    size_t i = ((size_t)blockIdx.x * blockDim.x + threadIdx.x) * 8;
    if (i >= n) return;
    float4 f0 = *(const float4*)(src + i);
    float4 f1 = *(const float4*)(src + i + 4);
    __half2 h[4];
    h[0] = __floats2half2_rn(f0.x, f0.y);
    h[1] = __floats2half2_rn(f0.z, f0.w);
    h[2] = __floats2half2_rn(f1.x, f1.y);
    h[3] = __floats2half2_rn(f1.z, f1.w);
    *(uint4*)(dst + i) = *(uint4*)h;
}

// ---------------- mask dtype detection -------------------------------------
__global__ void detect_mask_kernel(const unsigned char* __restrict__ m) {
    __shared__ int f0, f1;
    if (threadIdx.x == 0) { f0 = 0; f1 = 0; }
    __syncthreads();
    int lf = 0, lb = 0;
    for (int i = threadIdx.x; i < 4096; i += blockDim.x) {
        unsigned char c = m[i];
        if (c == 0x3Fu || c == 0x80u) lf = 1;
        if (c != 0u && (i & 3) != 0) lb = 1;
    }
    if (lf) atomicOr(&f0, 1);
    if (lb) atomicOr(&f1, 1);
    __syncthreads();
    if (threadIdx.x == 0) g_maskmode = f0 ? 2 : (f1 ? 0 : 1);
}

__device__ __forceinline__ bool load_mask(const void* m, int mode, size_t idx) {
    if (mode == 2) return ((const float*)m)[idx] != 0.0f;
    if (mode == 1) return ((const int*)m)[idx] != 0;
    return ((const unsigned char*)m)[idx] != 0u;
}

// ---------------- effective map weights ------------------------------------
__global__ void weff_kernel(const float* __restrict__ Wq,
                            const float* __restrict__ Wk,
                            const float* __restrict__ Wmap) {
    int t = blockIdx.x * blockDim.x + threadIdx.x;
    if (t >= 2 * H_ * DM_) return;
    int isK = t >= H_ * DM_;
    int r = isK ? (t - H_ * DM_) : t;
    int h = r / DM_, dm = r % DM_;
    const float* W  = isK ? Wk : Wq;
    const float* wm = Wmap + (isK ? DK_ : 0);
    float s = 0.f;
    #pragma unroll 8
    for (int d = 0; d < DK_; d++)
        s += wm[d] * W[(size_t)(h * DK_ + d) * DM_ + dm];
    if (isK) g_wkeff[r] = s; else g_wqeff[r] = s;
}

// ---------------- fused scores + softmax + attn write ----------------------
__global__ __launch_bounds__(256) void attn_kernel(
    const float* __restrict__ qin, const float* __restrict__ kin,
    const void* __restrict__ mask, float* __restrict__ attn_buf)
{
    __shared__ float wS[2 * H_ * DM_];
    __shared__ float sqS[H_ * LQ_];
    __shared__ float skS[H_ * LK_];
    const int b = blockIdx.x;
    const int tid = threadIdx.x, warp = tid >> 5, lane = tid & 31;

    for (int i = tid; i < H_ * DM_; i += 256) {
        wS[i]            = g_wqeff[i];
        wS[H_ * DM_ + i] = g_wkeff[i];
    }
    __syncthreads();

    for (int j = warp; j < LQ_ + LK_; j += 8) {
        const float* vec;
        const float* wf;
        if (j < LQ_) { vec = qin + ((size_t)b * LQ_ + j) * DM_;         wf = wS; }
        else         { vec = kin + ((size_t)b * LK_ + (j - LQ_)) * DM_; wf = wS + H_ * DM_; }
        float s0 = 0.f, s1 = 0.f, s2 = 0.f, s3 = 0.f;
        for (int idx = lane; idx < DM_; idx += 32) {
            float x = vec[idx];
            s0 += x * wf[idx];
            s1 += x * wf[DM_ + idx];
            s2 += x * wf[2 * DM_ + idx];
            s3 += x * wf[3 * DM_ + idx];
        }
        #pragma unroll
        for (int o = 16; o; o >>= 1) {
            s0 += __shfl_xor_sync(0xffffffffu, s0, o);
            s1 += __shfl_xor_sync(0xffffffffu, s1, o);
            s2 += __shfl_xor_sync(0xffffffffu, s2, o);
            s3 += __shfl_xor_sync(0xffffffffu, s3, o);
        }
        if (lane == 0) {
            if (j < LQ_) {
                sqS[0 * LQ_ + j] = s0; sqS[1 * LQ_ + j] = s1;
                sqS[2 * LQ_ + j] = s2; sqS[3 * LQ_ + j] = s3;
            } else {
                int kk = j - LQ_;
                skS[0 * LK_ + kk] = s0; skS[1 * LK_ + kk] = s1;
                skS[2 * LK_ + kk] = s2; skS[3 * LK_ + kk] = s3;
            }
        }
    }
    __syncthreads();

    const int mm = g_maskmode;
    for (int r = warp; r < H_ * LQ_; r += 8) {
        const int h = r >> 5, qq = r & 31;
        const float sq = sqS[r];
        const size_t mbase = ((size_t)b * LQ_ + qq) * LK_;
        bool m0 = load_mask(mask, mm, mbase + lane);
        bool m1 = load_mask(mask, mm, mbase + lane + 32);
        float v0 = m0 ? -1e10f : sq + skS[h * LK_ + lane];
        float v1 = m1 ? -1e10f : sq + skS[h * LK_ + lane + 32];
        float mx = fmaxf(v0, v1);
        #pragma unroll
        for (int o = 16; o; o >>= 1) mx = fmaxf(mx, __shfl_xor_sync(0xffffffffu, mx, o));
        float p0 = expf(v0 - mx), p1 = expf(v1 - mx);
        float sm = p0 + p1;
        #pragma unroll
        for (int o = 16; o; o >>= 1) sm += __shfl_xor_sync(0xffffffffu, sm, o);
        float inv = 1.0f / sm;
        p0 *= inv; p1 *= inv;
        const size_t ob = (((size_t)h * B_ + b) * LQ_ + qq) * LK_;
        attn_buf[ob + lane]      = p0;
        attn_buf[ob + lane + 32] = p1;
    }
}

// ---------------- bias + leakyReLU + residual + LayerNorm ------------------
__global__ __launch_bounds__(128) void epilogue_kernel(
    const float* __restrict__ qin, const float* __restrict__ fcb,
    const float* __restrict__ gamma, const float* __restrict__ beta,
    float* __restrict__ out)
{
    const int row = blockIdx.x;
    const int tid = threadIdx.x;
    __shared__ float rs[8];
    float y[4];
    float s = 0.f, s2 = 0.f;
    #pragma unroll
    for (int i = 0; i < 4; i++) {
        int j = tid + i * 128;
        float x = __half2float(g_fch[(size_t)row * DM_ + j]) + fcb[j];
        x = (x >= 0.f) ? x : 0.2f * x;
        x += qin[(size_t)row * DM_ + j];
        y[i] = x; s += x; s2 += x * x;
    }
    #pragma unroll
    for (int o = 16; o; o >>= 1) {
        s  += __shfl_xor_sync(0xffffffffu, s, o);
        s2 += __shfl_xor_sync(0xffffffffu, s2, o);
    }
    const int warp = tid >> 5, lane = tid & 31;
    if (lane == 0) { rs[warp] = s; rs[4 + warp] = s2; }
    __syncthreads();
    s  = rs[0] + rs[1] + rs[2] + rs[3];
    s2 = rs[4] + rs[5] + rs[6] + rs[7];
    const float mu  = s * (1.0f / DM_);
    const float var = s2 * (1.0f / DM_) - mu * mu;
    const float inv = rsqrtf(var + 1e-5f);
    #pragma unroll
    for (int i = 0; i < 4; i++) {
        int j = tid + i * 128;
        out[(size_t)row * DM_ + j] = gamma[j] * (y[i] - mu) * inv + beta[j];
    }
}

// ---------------- launch ----------------------------------------------------
extern "C" void kernel_launch(void* const* d_in, const int* in_sizes, int n_in,
                              void* d_out, int out_size)
{
    const float* q    = (const float*)d_in[0];
    const float* k    = (const float*)d_in[1];
    const float* v    = (const float*)d_in[2];
    const void*  mask =               d_in[3];
    const float* Wq   = (const float*)d_in[4];
    const float* Wk   = (const float*)d_in[5];
    const float* Wv   = (const float*)d_in[6];
    const float* Wmap = (const float*)d_in[7];
    const float* fcW  = (const float*)d_in[8];
    const float* fcb  = (const float*)d_in[9];
    const float* gma  = (const float*)d_in[10];
    const float* bta  = (const float*)d_in[11];
    float* out = (float*)d_out;

    const size_t out_elems  = (size_t)B_ * LQ_ * DM_;
    const size_t attn_elems = (size_t)H_ * B_ * LQ_ * LK_;
    int write_attn = ((size_t)out_size >= out_elems + attn_elems) ? 1 : 0;

    void *p_vh = nullptr, *p_wvh = nullptr, *p_fcwh = nullptr;
    void *p_oh = nullptr, *p_fch = nullptr, *p_attn = nullptr;
    cudaGetSymbolAddress(&p_vh, g_vh);
    cudaGetSymbolAddress(&p_wvh, g_wvh);
    cudaGetSymbolAddress(&p_fcwh, g_fcwh);
    cudaGetSymbolAddress(&p_oh, g_oh);
    cudaGetSymbolAddress(&p_fch, g_fch);
    cudaGetSymbolAddress(&p_attn, g_attn);

    // canonical attn buffer: the output region when present, else scratch
    float* attn_buf = write_attn ? (out + out_elems) : (float*)p_attn;

    cudaFuncSetAttribute(hgemm_av, cudaFuncAttributeMaxDynamicSharedMemorySize, GEMM_SMEM);
    cudaFuncSetAttribute(hgemm<__half>, cudaFuncAttributeMaxDynamicSharedMemorySize, GEMM_SMEM);

    detect_mask_kernel<<<1, 256>>>((const unsigned char*)mask);
    weff_kernel<<<(2 * H_ * DM_ + 255) / 256, 256>>>(Wq, Wk, Wmap);

    // convert v, Wv, fcW to fp16
    {
        size_t nv = (size_t)B_ * LK_ * DM_;
        conv_f2h_kernel<<<(unsigned)(nv / (256 * 8)), 256>>>(v, (__half*)p_vh, nv);
        size_t nw = (size_t)DM_ * DM_;
        conv_f2h_kernel<<<(unsigned)(nw / (256 * 8)), 256>>>(Wv, (__half*)p_wvh, nw);
        conv_f2h_kernel<<<(unsigned)(nw / (256 * 8)), 256>>>(fcW, (__half*)p_fcwh, nw);
    }

    attn_kernel<<<B_, 256>>>(q, k, mask, attn_buf);

    // fused: vp = v@Wv^T (per-tile) then O = attn @ vp  -> g_oh (fp16)
    {
        dim3 grid(DM_ / BN, (B_ * LK_) / BM);   // (4, 512)
        hgemm_av<<<grid, 128, GEMM_SMEM>>>((const __half*)p_vh, (const __half*)p_wvh,
                                           attn_buf, (__half*)p_oh);
    }

    // fc = oattn @ fcW^T -> g_fch (fp16)
    {
        dim3 grid(DM_ / BN, (B_ * LQ_) / BM);   // (4, 256)
        hgemm<__half><<<grid, 128, GEMM_SMEM>>>((const __half*)p_oh, (const __half*)p_fcwh,
                                                (__half*)p_fch);
    }

    epilogue_kernel<<<B_ * LQ_, 128>>>(q, fcb, gma, bta, out);
}